// round 1
// baseline (speedup 1.0000x reference)
#include <cuda_runtime.h>

#define NB 8
#define TDIM 4096
#define SDIM 512
#define CDIM 1024
#define NCHUNK 16
#define CHROWS (TDIM / NCHUNK) /* 256 */

#define NEG_INF (-3.0e38f)

// ---------------- scratch (static device globals; no allocation) ----------------
__device__ float g_scores[(size_t)NB * TDIM * SDIM];   // 67 MB: scores [B,T,S]
__device__ float g_vsc[(size_t)NB * SDIM * TDIM];      // 67 MB: v_scores [B,S,T]
__device__ float g_arm[NB * TDIM];                     // att row max
__device__ float g_ars[NB * TDIM];                     // att row sumexp
__device__ float g_pcm[NB * NCHUNK * SDIM];            // partial col max
__device__ float g_pcs[NB * NCHUNK * SDIM];            // partial col sumexp
__device__ float g_cm[NB * SDIM];                      // col max
__device__ float g_cs[NB * SDIM];                      // col sumexp
__device__ float g_vm[NB * SDIM];                      // v row max
__device__ float g_vsum[NB * SDIM];                    // v row sumexp

// ---------------------------------------------------------------------------
// Generic tiled SGEMM, 128x128x16, 256 threads, 8x8 microtile (4+4 split),
// double-buffered smem with register prefetch.
//
// MODE 0: scores = scale * X[T,C] * K[S,C]^T          (A row-major, B NT)
// MODE 1: att    = rowsoftmax(scores) * V[S,C]        (A row-major + softmax, B NN)
// MODE 2: k_t    = k + colsoftmax(scores)^T * X       (A col-access + softmax, B NN, add)
// MODE 3: vsc    = scale * V[S,C] * X[T,C]^T          (A row-major, B NT)
// MODE 4: v_t    = v + rowsoftmax(vsc) * X            (A row-major + softmax, B NN, add)
// ---------------------------------------------------------------------------
template <int MODE>
__global__ __launch_bounds__(256, 2)
void gemm_k(const float* __restrict__ Ag, const float* __restrict__ Bg,
            const float* __restrict__ Dg, float* __restrict__ Cg,
            const float* __restrict__ mxg, const float* __restrict__ smg,
            int M, int N, int K, float scale,
            int sA, int sB, int sC, int sD, int sS)
{
    constexpr int BM = 128, BN = 128, BK = 16, PAD = 4;
    constexpr bool A_COL   = (MODE == 2);
    constexpr bool A_SM    = (MODE == 1 || MODE == 2 || MODE == 4);
    constexpr bool B_NT    = (MODE == 0 || MODE == 3);
    constexpr bool EPI_ADD = (MODE == 2 || MODE == 4);

    __shared__ float As[2][BK][BM + PAD];
    __shared__ float Bs[2][BK][BN + PAD];

    const int tid = threadIdx.x;
    const int b   = blockIdx.z;
    const int m0  = blockIdx.y * BM;
    const int n0  = blockIdx.x * BN;
    const int lda = A_COL ? M : K;
    const int ldb = B_NT ? K : N;

    const float* A  = Ag + (size_t)b * sA;
    const float* B  = Bg + (size_t)b * sB;
    const float* MX = A_SM ? (mxg + (size_t)b * sS) : nullptr;
    const float* SM = A_SM ? (smg + (size_t)b * sS) : nullptr;

    float4 ra[2], rb[2];
    float4 rmx4[2], rss4[2];
    float  rmx[2], rss[2];

    auto loadRegs = [&](int k0) {
#pragma unroll
        for (int i = 0; i < 2; i++) {
            int v = tid + i * 256;
            if constexpr (!A_COL) {
                int r = v >> 2, c4 = (v & 3) << 2;
                ra[i] = *(const float4*)(A + (size_t)(m0 + r) * lda + k0 + c4);
                if constexpr (A_SM) { rmx[i] = MX[m0 + r]; rss[i] = SM[m0 + r]; }
            } else {
                int kk = v >> 5, c4 = (v & 31) << 2;
                ra[i]   = *(const float4*)(A + (size_t)(k0 + kk) * lda + m0 + c4);
                rmx4[i] = *(const float4*)(MX + m0 + c4);
                rss4[i] = *(const float4*)(SM + m0 + c4);
            }
            if constexpr (B_NT) {
                int r = v >> 2, c4 = (v & 3) << 2;
                rb[i] = *(const float4*)(B + (size_t)(n0 + r) * ldb + k0 + c4);
            } else {
                int kk = v >> 5, c4 = (v & 31) << 2;
                rb[i] = *(const float4*)(B + (size_t)(k0 + kk) * ldb + n0 + c4);
            }
        }
    };

    auto storeSmem = [&](int buf) {
#pragma unroll
        for (int i = 0; i < 2; i++) {
            int v = tid + i * 256;
            if constexpr (!A_COL) {
                int r = v >> 2, c4 = (v & 3) << 2;
                float f[4] = {ra[i].x, ra[i].y, ra[i].z, ra[i].w};
                if constexpr (A_SM) {
                    float inv = __fdividef(1.0f, rss[i]);
#pragma unroll
                    for (int j = 0; j < 4; j++) f[j] = __expf(f[j] - rmx[i]) * inv;
                }
#pragma unroll
                for (int j = 0; j < 4; j++) As[buf][c4 + j][r] = f[j];
            } else {
                int kk = v >> 5, c4 = (v & 31) << 2;
                float4 e;
                e.x = __expf(ra[i].x - rmx4[i].x) * __fdividef(1.0f, rss4[i].x);
                e.y = __expf(ra[i].y - rmx4[i].y) * __fdividef(1.0f, rss4[i].y);
                e.z = __expf(ra[i].z - rmx4[i].z) * __fdividef(1.0f, rss4[i].z);
                e.w = __expf(ra[i].w - rmx4[i].w) * __fdividef(1.0f, rss4[i].w);
                *(float4*)&As[buf][kk][c4] = e;
            }
            if constexpr (B_NT) {
                int r = v >> 2, c4 = (v & 3) << 2;
                Bs[buf][c4 + 0][r] = rb[i].x;
                Bs[buf][c4 + 1][r] = rb[i].y;
                Bs[buf][c4 + 2][r] = rb[i].z;
                Bs[buf][c4 + 3][r] = rb[i].w;
            } else {
                int kk = v >> 5, c4 = (v & 31) << 2;
                *(float4*)&Bs[buf][kk][c4] = rb[i];
            }
        }
    };

    float acc[8][8];
#pragma unroll
    for (int i = 0; i < 8; i++)
#pragma unroll
        for (int j = 0; j < 8; j++) acc[i][j] = 0.f;

    const int tx = tid & 15, ty = tid >> 4;

    auto compute = [&](int buf) {
#pragma unroll
        for (int kk = 0; kk < BK; kk++) {
            float4 a0 = *(float4*)&As[buf][kk][ty * 4];
            float4 a1 = *(float4*)&As[buf][kk][64 + ty * 4];
            float4 b0 = *(float4*)&Bs[buf][kk][tx * 4];
            float4 b1 = *(float4*)&Bs[buf][kk][64 + tx * 4];
            float a[8] = {a0.x, a0.y, a0.z, a0.w, a1.x, a1.y, a1.z, a1.w};
            float bb[8] = {b0.x, b0.y, b0.z, b0.w, b1.x, b1.y, b1.z, b1.w};
#pragma unroll
            for (int i = 0; i < 8; i++)
#pragma unroll
                for (int j = 0; j < 8; j++) acc[i][j] += a[i] * bb[j];
        }
    };

    loadRegs(0);
    storeSmem(0);
    __syncthreads();

    const int KT = K / BK;
    int buf = 0;
    for (int kt = 0; kt < KT; kt++) {
        if (kt + 1 < KT) loadRegs((kt + 1) * BK);
        compute(buf);
        if (kt + 1 < KT) {
            __syncthreads();
            storeSmem(buf ^ 1);
            __syncthreads();
            buf ^= 1;
        }
    }

    float* C = Cg + (size_t)b * sC;
    const float* D = EPI_ADD ? (Dg + (size_t)b * sD) : nullptr;
#pragma unroll
    for (int i = 0; i < 8; i++) {
        int r = m0 + ((i < 4) ? (ty * 4 + i) : (64 + ty * 4 + i - 4));
#pragma unroll
        for (int h = 0; h < 2; h++) {
            int c = n0 + (h ? (64 + tx * 4) : (tx * 4));
            float4 o;
            o.x = acc[i][h * 4 + 0] * scale;
            o.y = acc[i][h * 4 + 1] * scale;
            o.z = acc[i][h * 4 + 2] * scale;
            o.w = acc[i][h * 4 + 3] * scale;
            if constexpr (EPI_ADD) {
                float4 d = *(const float4*)(D + (size_t)r * N + c);
                o.x += d.x; o.y += d.y; o.z += d.z; o.w += d.w;
            }
            *(float4*)(C + (size_t)r * N + c) = o;
        }
    }
}

// ---------------- softmax stats kernels ----------------

// rows of length 512 (scores [B*T, S]); warp per row
__global__ void rowstats512_k(const float* __restrict__ S, float* __restrict__ rm,
                              float* __restrict__ rs)
{
    int warp = threadIdx.x >> 5, lane = threadIdx.x & 31;
    size_t row = (size_t)blockIdx.x * 8 + warp;
    const float* p = S + row * SDIM;
    float v[16];
    float m = NEG_INF;
#pragma unroll
    for (int i = 0; i < 16; i++) { v[i] = p[lane + i * 32]; m = fmaxf(m, v[i]); }
#pragma unroll
    for (int o = 16; o > 0; o >>= 1) m = fmaxf(m, __shfl_xor_sync(0xffffffffu, m, o));
    float s = 0.f;
#pragma unroll
    for (int i = 0; i < 16; i++) s += __expf(v[i] - m);
#pragma unroll
    for (int o = 16; o > 0; o >>= 1) s += __shfl_xor_sync(0xffffffffu, s, o);
    if (!lane) { rm[row] = m; rs[row] = s; }
}

// column stats over T for scores [B,T,S]: stage 1 (per 256-row chunk)
__global__ void colpart_k(const float* __restrict__ S, float* __restrict__ pm,
                          float* __restrict__ ps)
{
    int b = blockIdx.y, ch = blockIdx.x, s = threadIdx.x;
    const float* p = S + (size_t)b * TDIM * SDIM + (size_t)ch * CHROWS * SDIM + s;
    float m = NEG_INF, sum = 0.f;
    for (int t = 0; t < CHROWS; t++) {
        float v = p[(size_t)t * SDIM];
        float nm = fmaxf(m, v);
        sum = sum * __expf(m - nm) + __expf(v - nm);
        m = nm;
    }
    int o = (b * NCHUNK + ch) * SDIM + s;
    pm[o] = m; ps[o] = sum;
}

// column stats stage 2 (combine 16 chunks)
__global__ void colcomb_k(const float* __restrict__ pm, const float* __restrict__ ps,
                          float* __restrict__ cm, float* __restrict__ cs)
{
    int b = blockIdx.x, s = threadIdx.x;
    float m = NEG_INF;
#pragma unroll
    for (int c = 0; c < NCHUNK; c++) m = fmaxf(m, pm[(b * NCHUNK + c) * SDIM + s]);
    float sum = 0.f;
#pragma unroll
    for (int c = 0; c < NCHUNK; c++)
        sum += ps[(b * NCHUNK + c) * SDIM + s] * __expf(pm[(b * NCHUNK + c) * SDIM + s] - m);
    cm[b * SDIM + s] = m;
    cs[b * SDIM + s] = sum;
}

// rows of length 4096 (v_scores [B*S, T]); block (256 thr) per row
__global__ void rowstats4096_k(const float* __restrict__ S, float* __restrict__ rm,
                               float* __restrict__ rs)
{
    __shared__ float sh[8];
    int tid = threadIdx.x, lane = tid & 31, warp = tid >> 5;
    size_t row = blockIdx.x;
    const float* p = S + row * TDIM;
    float v[16];
    float m = NEG_INF;
#pragma unroll
    for (int i = 0; i < 16; i++) { v[i] = p[tid + i * 256]; m = fmaxf(m, v[i]); }
#pragma unroll
    for (int o = 16; o > 0; o >>= 1) m = fmaxf(m, __shfl_xor_sync(0xffffffffu, m, o));
    if (!lane) sh[warp] = m;
    __syncthreads();
    if (tid < 8) {
        float t = sh[tid];
#pragma unroll
        for (int o = 4; o > 0; o >>= 1) t = fmaxf(t, __shfl_xor_sync(0xffu, t, o));
        if (!tid) sh[0] = t;
    }
    __syncthreads();
    m = sh[0];
    __syncthreads();
    float s = 0.f;
#pragma unroll
    for (int i = 0; i < 16; i++) s += __expf(v[i] - m);
#pragma unroll
    for (int o = 16; o > 0; o >>= 1) s += __shfl_xor_sync(0xffffffffu, s, o);
    if (!lane) sh[warp] = s;
    __syncthreads();
    if (tid < 8) {
        float t = sh[tid];
#pragma unroll
        for (int o = 4; o > 0; o >>= 1) t += __shfl_xor_sync(0xffu, t, o);
        if (!tid) { rm[row] = m; rs[row] = t; }
    }
}

// ---------------- launch ----------------
extern "C" void kernel_launch(void* const* d_in, const int* in_sizes, int n_in,
                              void* d_out, int out_size)
{
    const float* x   = (const float*)d_in[0];
    const float* kin = (const float*)d_in[1];
    const float* vin = (const float*)d_in[2];

    float* att = (float*)d_out;                                  // [B,T,C]
    float* ktv = att + (size_t)NB * TDIM * CDIM;                 // [B,S,C]
    float* vtv = ktv + (size_t)NB * SDIM * CDIM;                 // [B,S,C]

    float *sc, *vsc, *arm, *ars, *pcm, *pcs, *cm, *cs, *vm, *vsum;
    cudaGetSymbolAddress((void**)&sc,   g_scores);
    cudaGetSymbolAddress((void**)&vsc,  g_vsc);
    cudaGetSymbolAddress((void**)&arm,  g_arm);
    cudaGetSymbolAddress((void**)&ars,  g_ars);
    cudaGetSymbolAddress((void**)&pcm,  g_pcm);
    cudaGetSymbolAddress((void**)&pcs,  g_pcs);
    cudaGetSymbolAddress((void**)&cm,   g_cm);
    cudaGetSymbolAddress((void**)&cs,   g_cs);
    cudaGetSymbolAddress((void**)&vm,   g_vm);
    cudaGetSymbolAddress((void**)&vsum, g_vsum);

    const float scale = 0.03125f; // 1/sqrt(1024)

    // 1) scores = scale * X K^T
    gemm_k<0><<<dim3(SDIM / 128, TDIM / 128, NB), 256>>>(
        x, kin, nullptr, sc, nullptr, nullptr, TDIM, SDIM, CDIM, scale,
        TDIM * CDIM, SDIM * CDIM, TDIM * SDIM, 0, 0);

    // 2) att = rowsoftmax(scores) V
    rowstats512_k<<<NB * TDIM / 8, 256>>>(sc, arm, ars);
    gemm_k<1><<<dim3(CDIM / 128, TDIM / 128, NB), 256>>>(
        sc, vin, nullptr, att, arm, ars, TDIM, CDIM, SDIM, 1.0f,
        TDIM * SDIM, SDIM * CDIM, TDIM * CDIM, 0, TDIM);

    // 3) k_t = k + colsoftmax(scores)^T X
    colpart_k<<<dim3(NCHUNK, NB), 512>>>(sc, pcm, pcs);
    colcomb_k<<<NB, 512>>>(pcm, pcs, cm, cs);
    gemm_k<2><<<dim3(CDIM / 128, SDIM / 128, NB), 256>>>(
        sc, x, kin, ktv, cm, cs, SDIM, CDIM, TDIM, 1.0f,
        TDIM * SDIM, TDIM * CDIM, SDIM * CDIM, SDIM * CDIM, SDIM);

    // 4) v_scores = scale * V X^T
    gemm_k<3><<<dim3(TDIM / 128, SDIM / 128, NB), 256>>>(
        vin, x, nullptr, vsc, nullptr, nullptr, SDIM, TDIM, CDIM, scale,
        SDIM * CDIM, TDIM * CDIM, SDIM * TDIM, 0, 0);

    // 5) v_t = v + rowsoftmax(v_scores) X
    rowstats4096_k<<<NB * SDIM, 256>>>(vsc, vm, vsum);
    gemm_k<4><<<dim3(CDIM / 128, SDIM / 128, NB), 256>>>(
        vsc, x, vin, vtv, vm, vsum, SDIM, CDIM, TDIM, 1.0f,
        SDIM * TDIM, TDIM * CDIM, SDIM * CDIM, SDIM * CDIM, SDIM);
}

// round 3
// speedup vs baseline: 2.4336x; 2.4336x over previous
#include <cuda_runtime.h>
#include <cuda_bf16.h>
#include <cstdint>

#define NB 8
#define TDIM 4096
#define SDIM 512
#define CDIM 1024
#define NCHUNK 16
#define CHROWS (TDIM / NCHUNK)
#define NEG_INF (-3.0e38f)

typedef __nv_bfloat16 bf16;

// ---------------- scratch (static device globals; no allocation) ----------------
__device__ float g_sc [(size_t)NB * TDIM * SDIM];
__device__ float g_vsc[(size_t)NB * SDIM * TDIM];
__device__ __align__(16) bf16 g_Xh [(size_t)NB * TDIM * CDIM], g_Xl [(size_t)NB * TDIM * CDIM];
__device__ __align__(16) bf16 g_XTh[(size_t)NB * CDIM * TDIM], g_XTl[(size_t)NB * CDIM * TDIM];
__device__ __align__(16) bf16 g_Kh [(size_t)NB * SDIM * CDIM], g_Kl [(size_t)NB * SDIM * CDIM];
__device__ __align__(16) bf16 g_Vh [(size_t)NB * SDIM * CDIM], g_Vl [(size_t)NB * SDIM * CDIM];
__device__ __align__(16) bf16 g_VTh[(size_t)NB * CDIM * SDIM], g_VTl[(size_t)NB * CDIM * SDIM];
__device__ __align__(16) bf16 g_Ph [(size_t)NB * TDIM * SDIM], g_Pl [(size_t)NB * TDIM * SDIM];
__device__ __align__(16) bf16 g_P2h[(size_t)NB * SDIM * TDIM], g_P2l[(size_t)NB * SDIM * TDIM];
__device__ __align__(16) bf16 g_P3h[(size_t)NB * SDIM * TDIM], g_P3l[(size_t)NB * SDIM * TDIM];
__device__ float g_arm[NB * TDIM], g_ars[NB * TDIM];
__device__ float g_pcm[NB * NCHUNK * SDIM], g_pcs[NB * NCHUNK * SDIM];
__device__ float g_cm [NB * SDIM], g_cs [NB * SDIM];
__device__ float g_vm [NB * SDIM], g_vsum[NB * SDIM];

// ---------------- PTX helpers (sm_80-class only; no tcgen05) ----------------
__device__ __forceinline__ void cp16(uint32_t dst, const void* src) {
    asm volatile("cp.async.cg.shared.global [%0], [%1], 16;" :: "r"(dst), "l"(src));
}
__device__ __forceinline__ void cp_commit() {
    asm volatile("cp.async.commit_group;" ::: "memory");
}
template <int N>
__device__ __forceinline__ void cp_wait() {
    asm volatile("cp.async.wait_group %0;" :: "n"(N) : "memory");
}
__device__ __forceinline__ void ldsm4(uint32_t* r, uint32_t addr) {
    asm volatile("ldmatrix.sync.aligned.m8n8.x4.shared.b16 {%0,%1,%2,%3}, [%4];"
                 : "=r"(r[0]), "=r"(r[1]), "=r"(r[2]), "=r"(r[3]) : "r"(addr));
}
__device__ __forceinline__ void mma16816(float* d, const uint32_t* a, const uint32_t* b) {
    asm volatile(
        "mma.sync.aligned.m16n8k16.row.col.f32.bf16.bf16.f32 "
        "{%0,%1,%2,%3}, {%4,%5,%6,%7}, {%8,%9}, {%0,%1,%2,%3};"
        : "+f"(d[0]), "+f"(d[1]), "+f"(d[2]), "+f"(d[3])
        : "r"(a[0]), "r"(a[1]), "r"(a[2]), "r"(a[3]), "r"(b[0]), "r"(b[1]));
}
__device__ __forceinline__ void split1(float f, bf16& h, bf16& l) {
    h = __float2bfloat16_rn(f);
    l = __float2bfloat16_rn(f - __bfloat162float(h));
}

// ---------------------------------------------------------------------------
// bf16x3 emulated-fp32 GEMM on HMMA (mma.sync m16n8k16).
// D[128 x 128 tile of M x Nglob] = sum_k A[m,k]*B[n,k]; A,B given as hi/lo
// bf16 planes, K-major. Per K-chunk (32) loads Ah,Al,Bh,Bl and accumulates
// Ah*Bh + Al*Bh + Ah*Bl into fp32 registers. Optional residual add + scale.
// ---------------------------------------------------------------------------
#define ROWB 80                 // padded row stride bytes (32 bf16 -> 64B + 16B pad)
#define TILEB (128 * ROWB)      // 10240
#define STAGEB (4 * TILEB)      // Ah,Al,Bh,Bl = 40960

template <bool ADD>
__global__ void __launch_bounds__(256, 2)
mma_gemm(const bf16* __restrict__ Ah, const bf16* __restrict__ Al,
         const bf16* __restrict__ Bh, const bf16* __restrict__ Bl,
         const float* __restrict__ Res, float* __restrict__ C,
         float scale, int K, int Nglob, size_t sA, size_t sB, size_t sC)
{
    extern __shared__ char dsm[];
    const uint32_t sbase = (uint32_t)__cvta_generic_to_shared(dsm);
    const int tid = threadIdx.x, wid = tid >> 5, lane = tid & 31;
    const int b = blockIdx.z, m0 = blockIdx.y * 128, n0 = blockIdx.x * 128;
    const int wm = wid & 1, wn = wid >> 1;          // warp tile: 64(M) x 32(N)

    const bf16* pA[2] = {Ah + (size_t)b * sA, Al + (size_t)b * sA};
    const bf16* pB[2] = {Bh + (size_t)b * sB, Bl + (size_t)b * sB};

    const int KT = K >> 5;   // chunks of 32

    // cp.async mapping: per tile, 512 x 16B chunks; each thread does 2.
    int cr[2], cc[2];
#pragma unroll
    for (int i = 0; i < 2; i++) {
        int id = tid + i * 256;
        cr[i] = id >> 2;          // row 0..127
        cc[i] = id & 3;           // 16B chunk 0..3
    }

    auto load = [&](int kc, int buf) {
        uint32_t st = sbase + buf * STAGEB;
        const bf16* src;
#pragma unroll
        for (int t = 0; t < 4; t++) {
            src = (t < 2) ? pA[t] : pB[t - 2];
            int rbase = (t < 2) ? m0 : n0;
            uint32_t tb = st + t * TILEB;
#pragma unroll
            for (int i = 0; i < 2; i++) {
                cp16(tb + cr[i] * ROWB + cc[i] * 16,
                     (const char*)src + ((size_t)(rbase + cr[i]) * K + kc * 32 + cc[i] * 8) * 2);
            }
        }
        cp_commit();
    };

    float acc[4][4][4];
#pragma unroll
    for (int mi = 0; mi < 4; mi++)
#pragma unroll
        for (int ni = 0; ni < 4; ni++)
#pragma unroll
            for (int j = 0; j < 4; j++) acc[mi][ni][j] = 0.f;

    // ldmatrix lane-address components (within a tile)
    const uint32_t a_off = (uint32_t)((wm * 64 + (lane & 15)) * ROWB + (lane >> 4) * 16);
    const uint32_t b_row = (uint32_t)(wn * 32 + (lane & 7) + ((lane >> 4) << 3));
    const uint32_t b_off = b_row * ROWB + ((lane >> 3) & 1) * 16;

    load(0, 0);

    for (int ci = 0; ci < KT; ci++) {
        int buf = ci & 1;
        if (ci + 1 < KT) { load(ci + 1, buf ^ 1); cp_wait<1>(); }
        else             { cp_wait<0>(); }
        __syncthreads();

        uint32_t st = sbase + buf * STAGEB;
        uint32_t ahb = st + a_off;
        uint32_t alb = st + TILEB + a_off;
        uint32_t bhb = st + 2 * TILEB + b_off;
        uint32_t blb = st + 3 * TILEB + b_off;

#pragma unroll
        for (int ks = 0; ks < 2; ks++) {          // two k16 steps per chunk
            uint32_t ah[4][4], al[4][4];
#pragma unroll
            for (int mi = 0; mi < 4; mi++) {
                ldsm4(ah[mi], ahb + mi * (16 * ROWB) + ks * 32);
                ldsm4(al[mi], alb + mi * (16 * ROWB) + ks * 32);
            }
#pragma unroll
            for (int j = 0; j < 2; j++) {         // n-tile pairs (16 cols each)
                uint32_t bh[4], bl[4];
                ldsm4(bh, bhb + j * (16 * ROWB) + ks * 32);
                ldsm4(bl, blb + j * (16 * ROWB) + ks * 32);
#pragma unroll
                for (int mi = 0; mi < 4; mi++) {
                    mma16816(acc[mi][2 * j],     ah[mi], bh);
                    mma16816(acc[mi][2 * j],     al[mi], bh);
                    mma16816(acc[mi][2 * j],     ah[mi], bl);
                    mma16816(acc[mi][2 * j + 1], ah[mi], bh + 2);
                    mma16816(acc[mi][2 * j + 1], al[mi], bh + 2);
                    mma16816(acc[mi][2 * j + 1], ah[mi], bl + 2);
                }
            }
        }
        __syncthreads();
    }

    // epilogue: direct float2 stores (+ residual)
    float* Co = C + (size_t)b * sC;
    const float* Rp = ADD ? (Res + (size_t)b * sC) : nullptr;
    const int rbase = m0 + wm * 64 + (lane >> 2);
    const int cbase = n0 + wn * 32 + (lane & 3) * 2;
#pragma unroll
    for (int mi = 0; mi < 4; mi++) {
#pragma unroll
        for (int ni = 0; ni < 4; ni++) {
#pragma unroll
            for (int h = 0; h < 2; h++) {         // h=0 -> rows +0, h=1 -> rows +8
                int r = rbase + mi * 16 + h * 8;
                int c = cbase + ni * 8;
                float2 v;
                v.x = acc[mi][ni][2 * h]     * scale;
                v.y = acc[mi][ni][2 * h + 1] * scale;
                size_t go = (size_t)r * Nglob + c;
                if (ADD) {
                    float2 d = *(const float2*)(Rp + go);
                    v.x += d.x; v.y += d.y;
                }
                *(float2*)(Co + go) = v;
            }
        }
    }
}

// ---------------- conversion kernels ----------------
__global__ void split_k(const float* __restrict__ in, bf16* __restrict__ h,
                        bf16* __restrict__ l, size_t n4)
{
    size_t i = (size_t)blockIdx.x * blockDim.x + threadIdx.x;
    if (i >= n4) return;
    float4 v = ((const float4*)in)[i];
    bf16 h0, l0, h1, l1, h2, l2, h3, l3;
    split1(v.x, h0, l0); split1(v.y, h1, l1); split1(v.z, h2, l2); split1(v.w, h3, l3);
    __nv_bfloat162* hp = (__nv_bfloat162*)h;
    __nv_bfloat162* lp = (__nv_bfloat162*)l;
    hp[i * 2]     = __nv_bfloat162(h0, h1);
    hp[i * 2 + 1] = __nv_bfloat162(h2, h3);
    lp[i * 2]     = __nv_bfloat162(l0, l1);
    lp[i * 2 + 1] = __nv_bfloat162(l2, l3);
}

__global__ void tsplit_k(const float* __restrict__ in, bf16* __restrict__ oh,
                         bf16* __restrict__ ol, int R, int Cc)
{
    __shared__ float t[32][33];
    int b = blockIdx.z;
    int c0 = blockIdx.x * 32, r0 = blockIdx.y * 32;
    const float* ip = in + (size_t)b * R * Cc;
    int tx = threadIdx.x, ty = threadIdx.y;
#pragma unroll
    for (int i = 0; i < 4; i++)
        t[ty + i * 8][tx] = ip[(size_t)(r0 + ty + i * 8) * Cc + c0 + tx];
    __syncthreads();
    size_t ob = (size_t)b * Cc * R;
#pragma unroll
    for (int i = 0; i < 4; i++) {
        int c = c0 + ty + i * 8;
        bf16 h, l;
        split1(t[tx][ty + i * 8], h, l);
        oh[ob + (size_t)c * R + r0 + tx] = h;
        ol[ob + (size_t)c * R + r0 + tx] = l;
    }
}

__global__ void pconv_k(const float* __restrict__ in, const float* __restrict__ rm,
                        const float* __restrict__ rs, bf16* __restrict__ oh,
                        bf16* __restrict__ ol, int Lq)
{
    size_t i = (size_t)blockIdx.x * blockDim.x + threadIdx.x;
    size_t row = i / Lq;
    float m = rm[row], inv = __fdividef(1.0f, rs[row]);
    float4 v = ((const float4*)in)[i];
    bf16 h0, l0, h1, l1, h2, l2, h3, l3;
    split1(__expf(v.x - m) * inv, h0, l0);
    split1(__expf(v.y - m) * inv, h1, l1);
    split1(__expf(v.z - m) * inv, h2, l2);
    split1(__expf(v.w - m) * inv, h3, l3);
    __nv_bfloat162* hp = (__nv_bfloat162*)oh;
    __nv_bfloat162* lp = (__nv_bfloat162*)ol;
    hp[i * 2]     = __nv_bfloat162(h0, h1);
    hp[i * 2 + 1] = __nv_bfloat162(h2, h3);
    lp[i * 2]     = __nv_bfloat162(l0, l1);
    lp[i * 2 + 1] = __nv_bfloat162(l2, l3);
}

__global__ void pcolT_k(const float* __restrict__ sc, const float* __restrict__ cm,
                        const float* __restrict__ cs, bf16* __restrict__ oh,
                        bf16* __restrict__ ol)
{
    __shared__ float t[32][33];
    int b = blockIdx.z;
    int s0 = blockIdx.x * 32, t0 = blockIdx.y * 32;
    const float* ip = sc + (size_t)b * TDIM * SDIM;
    int tx = threadIdx.x, ty = threadIdx.y;
#pragma unroll
    for (int i = 0; i < 4; i++)
        t[ty + i * 8][tx] = ip[(size_t)(t0 + ty + i * 8) * SDIM + s0 + tx];
    __syncthreads();
    size_t ob = (size_t)b * SDIM * TDIM;
#pragma unroll
    for (int i = 0; i < 4; i++) {
        int s = s0 + ty + i * 8;
        float m = cm[b * SDIM + s], inv = __fdividef(1.0f, cs[b * SDIM + s]);
        bf16 h, l;
        split1(__expf(t[tx][ty + i * 8] - m) * inv, h, l);
        oh[ob + (size_t)s * TDIM + t0 + tx] = h;
        ol[ob + (size_t)s * TDIM + t0 + tx] = l;
    }
}

// ---------------- softmax stats kernels ----------------
__global__ void rowstats512_k(const float* __restrict__ S, float* __restrict__ rm,
                              float* __restrict__ rs)
{
    int warp = threadIdx.x >> 5, lane = threadIdx.x & 31;
    size_t row = (size_t)blockIdx.x * 8 + warp;
    const float* p = S + row * SDIM;
    float v[16];
    float m = NEG_INF;
#pragma unroll
    for (int i = 0; i < 16; i++) { v[i] = p[lane + i * 32]; m = fmaxf(m, v[i]); }
#pragma unroll
    for (int o = 16; o > 0; o >>= 1) m = fmaxf(m, __shfl_xor_sync(0xffffffffu, m, o));
    float s = 0.f;
#pragma unroll
    for (int i = 0; i < 16; i++) s += __expf(v[i] - m);
#pragma unroll
    for (int o = 16; o > 0; o >>= 1) s += __shfl_xor_sync(0xffffffffu, s, o);
    if (!lane) { rm[row] = m; rs[row] = s; }
}

__global__ void colpart_k(const float* __restrict__ S, float* __restrict__ pm,
                          float* __restrict__ ps)
{
    int b = blockIdx.y, ch = blockIdx.x, s = threadIdx.x;
    const float* p = S + (size_t)b * TDIM * SDIM + (size_t)ch * CHROWS * SDIM + s;
    float m = NEG_INF, sum = 0.f;
    for (int t = 0; t < CHROWS; t++) {
        float v = p[(size_t)t * SDIM];
        float nm = fmaxf(m, v);
        sum = sum * __expf(m - nm) + __expf(v - nm);
        m = nm;
    }
    int o = (b * NCHUNK + ch) * SDIM + s;
    pm[o] = m; ps[o] = sum;
}

__global__ void colcomb_k(const float* __restrict__ pm, const float* __restrict__ ps,
                          float* __restrict__ cm, float* __restrict__ cs)
{
    int b = blockIdx.x, s = threadIdx.x;
    float m = NEG_INF;
#pragma unroll
    for (int c = 0; c < NCHUNK; c++) m = fmaxf(m, pm[(b * NCHUNK + c) * SDIM + s]);
    float sum = 0.f;
#pragma unroll
    for (int c = 0; c < NCHUNK; c++)
        sum += ps[(b * NCHUNK + c) * SDIM + s] * __expf(pm[(b * NCHUNK + c) * SDIM + s] - m);
    cm[b * SDIM + s] = m;
    cs[b * SDIM + s] = sum;
}

__global__ void rowstats4096_k(const float* __restrict__ S, float* __restrict__ rm,
                               float* __restrict__ rs)
{
    __shared__ float sh[8];
    int tid = threadIdx.x, lane = tid & 31, warp = tid >> 5;
    size_t row = blockIdx.x;
    const float* p = S + row * TDIM;
    float v[16];
    float m = NEG_INF;
#pragma unroll
    for (int i = 0; i < 16; i++) { v[i] = p[tid + i * 256]; m = fmaxf(m, v[i]); }
#pragma unroll
    for (int o = 16; o > 0; o >>= 1) m = fmaxf(m, __shfl_xor_sync(0xffffffffu, m, o));
    if (!lane) sh[warp] = m;
    __syncthreads();
    if (tid < 8) {
        float t = sh[tid];
#pragma unroll
        for (int o = 4; o > 0; o >>= 1) t = fmaxf(t, __shfl_xor_sync(0xffu, t, o));
        if (!tid) sh[0] = t;
    }
    __syncthreads();
    m = sh[0];
    __syncthreads();
    float s = 0.f;
#pragma unroll
    for (int i = 0; i < 16; i++) s += __expf(v[i] - m);
#pragma unroll
    for (int o = 16; o > 0; o >>= 1) s += __shfl_xor_sync(0xffffffffu, s, o);
    if (!lane) sh[warp] = s;
    __syncthreads();
    if (tid < 8) {
        float t = sh[tid];
#pragma unroll
        for (int o = 4; o > 0; o >>= 1) t += __shfl_xor_sync(0xffu, t, o);
        if (!tid) { rm[row] = m; rs[row] = t; }
    }
}

// ---------------- launch ----------------
extern "C" void kernel_launch(void* const* d_in, const int* in_sizes, int n_in,
                              void* d_out, int out_size)
{
    const float* x   = (const float*)d_in[0];
    const float* kin = (const float*)d_in[1];
    const float* vin = (const float*)d_in[2];

    float* att = (float*)d_out;
    float* ktv = att + (size_t)NB * TDIM * CDIM;
    float* vtv = ktv + (size_t)NB * SDIM * CDIM;

    float *sc, *vsc, *arm, *ars, *pcm, *pcs, *cm, *cs, *vm, *vsum;
    bf16 *Xh, *Xl, *XTh, *XTl, *Kh, *Kl, *Vh, *Vl, *VTh, *VTl;
    bf16 *Ph, *Pl, *P2h, *P2l, *P3h, *P3l;
    cudaGetSymbolAddress((void**)&sc, g_sc);     cudaGetSymbolAddress((void**)&vsc, g_vsc);
    cudaGetSymbolAddress((void**)&arm, g_arm);   cudaGetSymbolAddress((void**)&ars, g_ars);
    cudaGetSymbolAddress((void**)&pcm, g_pcm);   cudaGetSymbolAddress((void**)&pcs, g_pcs);
    cudaGetSymbolAddress((void**)&cm, g_cm);     cudaGetSymbolAddress((void**)&cs, g_cs);
    cudaGetSymbolAddress((void**)&vm, g_vm);     cudaGetSymbolAddress((void**)&vsum, g_vsum);
    cudaGetSymbolAddress((void**)&Xh, g_Xh);     cudaGetSymbolAddress((void**)&Xl, g_Xl);
    cudaGetSymbolAddress((void**)&XTh, g_XTh);   cudaGetSymbolAddress((void**)&XTl, g_XTl);
    cudaGetSymbolAddress((void**)&Kh, g_Kh);     cudaGetSymbolAddress((void**)&Kl, g_Kl);
    cudaGetSymbolAddress((void**)&Vh, g_Vh);     cudaGetSymbolAddress((void**)&Vl, g_Vl);
    cudaGetSymbolAddress((void**)&VTh, g_VTh);   cudaGetSymbolAddress((void**)&VTl, g_VTl);
    cudaGetSymbolAddress((void**)&Ph, g_Ph);     cudaGetSymbolAddress((void**)&Pl, g_Pl);
    cudaGetSymbolAddress((void**)&P2h, g_P2h);   cudaGetSymbolAddress((void**)&P2l, g_P2l);
    cudaGetSymbolAddress((void**)&P3h, g_P3h);   cudaGetSymbolAddress((void**)&P3l, g_P3l);

    const int SMEM = 2 * STAGEB;  // 81920
    cudaFuncSetAttribute(mma_gemm<false>, cudaFuncAttributeMaxDynamicSharedMemorySize, SMEM);
    cudaFuncSetAttribute(mma_gemm<true>,  cudaFuncAttributeMaxDynamicSharedMemorySize, SMEM);

    const float scale = 0.03125f;  // 1/sqrt(1024)

    // operand splits / transposes
    {
        size_t n4 = (size_t)NB * TDIM * CDIM / 4;
        split_k<<<(unsigned)((n4 + 255) / 256), 256>>>(x, Xh, Xl, n4);
    }
    {
        size_t n4 = (size_t)NB * SDIM * CDIM / 4;
        split_k<<<(unsigned)((n4 + 255) / 256), 256>>>(kin, Kh, Kl, n4);
        split_k<<<(unsigned)((n4 + 255) / 256), 256>>>(vin, Vh, Vl, n4);
    }
    tsplit_k<<<dim3(CDIM / 32, TDIM / 32, NB), dim3(32, 8)>>>(x, XTh, XTl, TDIM, CDIM);
    tsplit_k<<<dim3(CDIM / 32, SDIM / 32, NB), dim3(32, 8)>>>(vin, VTh, VTl, SDIM, CDIM);

    // 1) scores = scale * X K^T  [T,S]
    mma_gemm<false><<<dim3(SDIM / 128, TDIM / 128, NB), 256, SMEM>>>(
        Xh, Xl, Kh, Kl, nullptr, sc, scale, CDIM, SDIM,
        (size_t)TDIM * CDIM, (size_t)SDIM * CDIM, (size_t)TDIM * SDIM);

    // softmax stats
    rowstats512_k<<<NB * TDIM / 8, 256>>>(sc, arm, ars);
    colpart_k<<<dim3(NCHUNK, NB), 512>>>(sc, pcm, pcs);
    colcomb_k<<<NB, 512>>>(pcm, pcs, cm, cs);

    // P (row softmax), P2^T (col softmax transposed)
    {
        size_t n4 = (size_t)NB * TDIM * SDIM / 4;
        pconv_k<<<(unsigned)((n4 + 255) / 256), 256>>>(sc, arm, ars, Ph, Pl, SDIM / 4);
    }
    pcolT_k<<<dim3(SDIM / 32, TDIM / 32, NB), dim3(32, 8)>>>(sc, cm, cs, P2h, P2l);

    // 2) att = P V   (B = V^T [C,S], K=512)
    mma_gemm<false><<<dim3(CDIM / 128, TDIM / 128, NB), 256, SMEM>>>(
        Ph, Pl, VTh, VTl, nullptr, att, 1.0f, SDIM, CDIM,
        (size_t)TDIM * SDIM, (size_t)CDIM * SDIM, (size_t)TDIM * CDIM);

    // 3) k_t = k + P2^T X   (B = X^T [C,T], K=4096)
    mma_gemm<true><<<dim3(CDIM / 128, SDIM / 128, NB), 256, SMEM>>>(
        P2h, P2l, XTh, XTl, kin, ktv, 1.0f, TDIM, CDIM,
        (size_t)SDIM * TDIM, (size_t)CDIM * TDIM, (size_t)SDIM * CDIM);

    // 4) v_scores = scale * V X^T  [S,T]
    mma_gemm<false><<<dim3(TDIM / 128, SDIM / 128, NB), 256, SMEM>>>(
        Vh, Vl, Xh, Xl, nullptr, vsc, scale, CDIM, TDIM,
        (size_t)SDIM * CDIM, (size_t)TDIM * CDIM, (size_t)SDIM * TDIM);

    // P3 (row softmax of v_scores)
    rowstats4096_k<<<NB * SDIM, 256>>>(vsc, vm, vsum);
    {
        size_t n4 = (size_t)NB * SDIM * TDIM / 4;
        pconv_k<<<(unsigned)((n4 + 255) / 256), 256>>>(vsc, vm, vsum, P3h, P3l, TDIM / 4);
    }

    // 5) v_t = v + P3 X   (B = X^T [C,T], K=4096)
    mma_gemm<true><<<dim3(CDIM / 128, SDIM / 128, NB), 256, SMEM>>>(
        P3h, P3l, XTh, XTl, vin, vtv, 1.0f, TDIM, CDIM,
        (size_t)SDIM * TDIM, (size_t)CDIM * TDIM, (size_t)SDIM * CDIM);
}